// round 15
// baseline (speedup 1.0000x reference)
#include <cuda_runtime.h>
#include <cuda_bf16.h>
#include <cstdint>

#define NN 10000
#define EE 160000
#define DD 128
#define HH 8
#define HC 1024
#define FFD 512

// ---------------- scratch ----------------------------------------------------
static __device__ __align__(16) __nv_bfloat16 d_qb[NN * HC];
static __device__ __align__(16) __nv_bfloat16 d_kb[NN * HC];
static __device__ __align__(16) __nv_bfloat16 d_vb[NN * HC];
static __device__ __align__(16) float d_skip[NN * DD];   // holds x + x@Wskip + bskip
static __device__ __align__(16) float d_h[NN * DD];
static __device__ __align__(16) float d_part[4 * NN * DD];   // FFN2 split-K partials
static __device__ int d_deg[NN];
static __device__ int d_off[NN + 1];
static __device__ int d_cur[NN];
static __device__ int d_ssrc[EE];
static __device__ int d_is64;

// bf16 split buffers (A' = [hi|hi|lo] along K, B' = [hi;lo;hi] along K)
static __device__ __align__(16) __nv_bfloat16 d_A2x[NN * 3 * DD];
static __device__ __align__(16) __nv_bfloat16 d_A2h[NN * 3 * DD];
static __device__ __align__(16) __nv_bfloat16 d_A2f[NN * 3 * FFD];
static __device__ __align__(16) __nv_bfloat16 d_B2q[3 * DD * HC];
static __device__ __align__(16) __nv_bfloat16 d_B2k[3 * DD * HC];
static __device__ __align__(16) __nv_bfloat16 d_B2v[3 * DD * HC];
static __device__ __align__(16) __nv_bfloat16 d_B2s[3 * DD * DD];
static __device__ __align__(16) __nv_bfloat16 d_B2w1[3 * DD * FFD];
static __device__ __align__(16) __nv_bfloat16 d_B2w2[3 * FFD * DD];

// ---------------- edge dtype detect ------------------------------------------
__global__ void detect_kernel(const void* ei) {
    if (blockIdx.x == 0 && threadIdx.x == 0) {
        const unsigned int* w = (const unsigned int*)ei;
        int is64 = 1;
        for (int j = 0; j < 64; ++j) {
            if (w[2 * j + 1] != 0u) { is64 = 0; break; }
        }
        d_is64 = is64;
    }
}

__device__ __forceinline__ int edge_val(const void* ei, int idx) {
    return d_is64 ? (int)((const long long*)ei)[idx] : ((const int*)ei)[idx];
}

// d_deg / d_cur zeroed statically on first use, re-zeroed in ln2_reduce.
__global__ void hist_kernel(const void* __restrict__ ei) {
    int e = blockIdx.x * blockDim.x + threadIdx.x;
    if (e >= EE) return;
    atomicAdd(&d_deg[edge_val(ei, EE + e)], 1);
}

__global__ void scan_kernel() {
    __shared__ int sm[1024];
    int t = threadIdx.x;
    int base = t * 10;
    int loc[10];
    int run = 0;
#pragma unroll
    for (int j = 0; j < 10; ++j) {
        int idx = base + j;
        loc[j] = run;
        run += (idx < NN) ? d_deg[idx] : 0;
    }
    sm[t] = run;
    __syncthreads();
    for (int ofs = 1; ofs < 1024; ofs <<= 1) {
        int v = (t >= ofs) ? sm[t - ofs] : 0;
        __syncthreads();
        sm[t] += v;
        __syncthreads();
    }
    int pre = (t == 0) ? 0 : sm[t - 1];
#pragma unroll
    for (int j = 0; j < 10; ++j) {
        int idx = base + j;
        if (idx < NN) d_off[idx] = pre + loc[j];
    }
    if (t == 1023) d_off[NN] = sm[1023];
}

__global__ void scatter_kernel(const void* __restrict__ ei) {
    int e = blockIdx.x * blockDim.x + threadIdx.x;
    if (e >= EE) return;
    int src = edge_val(ei, e);
    int dst = edge_val(ei, EE + e);
    int pos = atomicAdd(&d_cur[dst], 1);
    d_ssrc[d_off[dst] + pos] = src;
}

// ---------------- splits -----------------------------------------------------
#define SZX   (NN * DD)
#define SZQKV (DD * HC)
#define SZS   (DD * DD)
#define SZW1  (DD * FFD)
#define SZW2  (FFD * DD)
#define SPLIT_MAIN (SZX + 3 * SZQKV + SZS)
#define SPLIT_SIDE (SZW1 + SZW2)

__device__ __forceinline__ void put_splitB(const float* in, __nv_bfloat16* out,
                                           int idx, int K, int N) {
    int k = idx / N, n = idx - k * N;
    float a = in[idx];
    __nv_bfloat16 hi = __float2bfloat16(a);
    __nv_bfloat16 lo = __float2bfloat16(a - __bfloat162float(hi));
    out[(size_t)k * N + n] = hi;
    out[(size_t)(K + k) * N + n] = lo;
    out[(size_t)(2 * K + k) * N + n] = hi;
}

__global__ void splitMain_kernel(const float* x, const float* Wq,
                                 const float* Wk, const float* Wv,
                                 const float* Ws)
{
    int i = blockIdx.x * blockDim.x + threadIdx.x;
    if (i >= SPLIT_MAIN) return;
    if (i < SZX) {
        int m = i / DD, k = i - m * DD;
        float a = x[i];
        __nv_bfloat16 hi = __float2bfloat16(a);
        __nv_bfloat16 lo = __float2bfloat16(a - __bfloat162float(hi));
        __nv_bfloat16* o = d_A2x + (size_t)m * 3 * DD;
        o[k] = hi;
        o[DD + k] = hi;
        o[2 * DD + k] = lo;
        return;
    }
    int j = i - SZX;
    if (j < SZQKV)          put_splitB(Wq, d_B2q, j, DD, HC);
    else if (j < 2 * SZQKV) put_splitB(Wk, d_B2k, j - SZQKV, DD, HC);
    else if (j < 3 * SZQKV) put_splitB(Wv, d_B2v, j - 2 * SZQKV, DD, HC);
    else                    put_splitB(Ws, d_B2s, j - 3 * SZQKV, DD, DD);
}

__global__ void splitSide_kernel(const float* W1, const float* W2) {
    int i = blockIdx.x * blockDim.x + threadIdx.x;
    if (i >= SPLIT_SIDE) return;
    if (i < SZW1) put_splitB(W1, d_B2w1, i, DD, FFD);
    else          put_splitB(W2, d_B2w2, i - SZW1, FFD, DD);
}

// ---------------- bf16 tensor-core GEMM core (BK=64, 2-stage) ----------------
#define BM 128
#define BN 128
#define BK 64
#define ASTRIDE 72            // BK + 8
#define BSTRIDE 136           // BN + 8
#define STAGE_A (BM * ASTRIDE)    // 9216 bf16
#define STAGE_B (BK * BSTRIDE)    // 8704 bf16
#define GEMM_SMEM_BYTES (2 * (STAGE_A + STAGE_B) * 2)   // 71680 B

__device__ __forceinline__ uint32_t smem_u32(const void* p) {
    return (uint32_t)__cvta_generic_to_shared(p);
}

__device__ __forceinline__ void ldmatrix_x4(uint32_t& r0, uint32_t& r1,
                                            uint32_t& r2, uint32_t& r3,
                                            uint32_t addr) {
    asm volatile("ldmatrix.sync.aligned.m8n8.x4.shared.b16 {%0,%1,%2,%3}, [%4];"
                 : "=r"(r0), "=r"(r1), "=r"(r2), "=r"(r3) : "r"(addr));
}

__device__ __forceinline__ void ldmatrix_x4_trans(uint32_t& r0, uint32_t& r1,
                                                  uint32_t& r2, uint32_t& r3,
                                                  uint32_t addr) {
    asm volatile("ldmatrix.sync.aligned.m8n8.x4.trans.shared.b16 {%0,%1,%2,%3}, [%4];"
                 : "=r"(r0), "=r"(r1), "=r"(r2), "=r"(r3) : "r"(addr));
}

__device__ __forceinline__ void mma_bf16(float& c0, float& c1, float& c2, float& c3,
                                         uint32_t a0, uint32_t a1, uint32_t a2,
                                         uint32_t a3, uint32_t b0, uint32_t b1) {
    asm volatile(
        "mma.sync.aligned.m16n8k16.row.col.f32.bf16.bf16.f32 "
        "{%0,%1,%2,%3}, {%4,%5,%6,%7}, {%8,%9}, {%0,%1,%2,%3};"
        : "+f"(c0), "+f"(c1), "+f"(c2), "+f"(c3)
        : "r"(a0), "r"(a1), "r"(a2), "r"(a3), "r"(b0), "r"(b1));
}

__device__ __forceinline__ void cp_async16(uint32_t saddr, const void* gaddr,
                                           int src_sz) {
    asm volatile("cp.async.cg.shared.global [%0], [%1], 16, %2;"
                 :: "r"(saddr), "l"(gaddr), "r"(src_sz));
}

__device__ __forceinline__ void gemm_core(
    __nv_bfloat16* As, __nv_bfloat16* Bs,
    const __nv_bfloat16* __restrict__ A, int lda, int Kp,
    const __nv_bfloat16* __restrict__ B, int N,
    const float* __restrict__ bias, const float* __restrict__ res,
    float* Cf, __nv_bfloat16* Cb, __nv_bfloat16* Csplit,
    int M, int relu, int m0, int n0)
{
    int tid = threadIdx.x;
    int lane = tid & 31;
    int wid = tid >> 5;
    int wm = wid >> 2;
    int wn = wid & 3;

    float acc[4][4][4];
#pragma unroll
    for (int i = 0; i < 4; ++i)
#pragma unroll
        for (int j = 0; j < 4; ++j)
#pragma unroll
            for (int c = 0; c < 4; ++c) acc[i][j][c] = 0.0f;

    const int T = Kp / BK;

    auto load_stage = [&](int t, int buf) {
        int ko = t * BK;
        __nv_bfloat16* as = As + buf * STAGE_A;
        __nv_bfloat16* bs = Bs + buf * STAGE_B;
#pragma unroll
        for (int i = 0; i < 4; ++i) {
            int c = tid + i * 256;
            int row = c >> 3;
            int col = (c & 7) * 8;
            int gm = m0 + row;
            uint32_t s = smem_u32(as + row * ASTRIDE + col);
            const void* g = A + (size_t)gm * lda + ko + col;
            cp_async16(s, g, gm < M ? 16 : 0);
        }
#pragma unroll
        for (int i = 0; i < 4; ++i) {
            int c = tid + i * 256;
            int row = c >> 4;
            int col = (c & 15) * 8;
            uint32_t s = smem_u32(bs + row * BSTRIDE + col);
            const void* g = B + (size_t)(ko + row) * N + n0 + col;
            cp_async16(s, g, 16);
        }
        asm volatile("cp.async.commit_group;");
    };

    load_stage(0, 0);

    for (int t = 0; t < T; ++t) {
        if (t + 1 < T) {
            load_stage(t + 1, (t + 1) & 1);
            asm volatile("cp.async.wait_group 1;");
        } else {
            asm volatile("cp.async.wait_group 0;");
        }
        __syncthreads();

        int buf = t & 1;
        const __nv_bfloat16* as = As + buf * STAGE_A;
        const __nv_bfloat16* bs = Bs + buf * STAGE_B;
#pragma unroll
        for (int ks = 0; ks < 4; ++ks) {
            uint32_t a[4][4];
#pragma unroll
            for (int mt = 0; mt < 4; ++mt) {
                int row = wm * 64 + mt * 16 + (lane & 15);
                int col = ks * 16 + ((lane >> 4) << 3);
                ldmatrix_x4(a[mt][0], a[mt][1], a[mt][2], a[mt][3],
                            smem_u32(as + row * ASTRIDE + col));
            }
            uint32_t b[2][4];
#pragma unroll
            for (int n16 = 0; n16 < 2; ++n16) {
                int row = ks * 16 + (lane & 15);
                int col = wn * 32 + n16 * 16 + ((lane >> 4) << 3);
                ldmatrix_x4_trans(b[n16][0], b[n16][1], b[n16][2], b[n16][3],
                                  smem_u32(bs + row * BSTRIDE + col));
            }
#pragma unroll
            for (int mt = 0; mt < 4; ++mt)
#pragma unroll
                for (int nt = 0; nt < 4; ++nt) {
                    mma_bf16(acc[mt][nt][0], acc[mt][nt][1],
                             acc[mt][nt][2], acc[mt][nt][3],
                             a[mt][0], a[mt][1], a[mt][2], a[mt][3],
                             b[nt >> 1][(nt & 1) * 2],
                             b[nt >> 1][(nt & 1) * 2 + 1]);
                }
        }
        __syncthreads();
    }

    int gr = lane >> 2;
    int gc = (lane & 3) * 2;
#pragma unroll
    for (int mt = 0; mt < 4; ++mt) {
        int row = m0 + wm * 64 + mt * 16 + gr;
#pragma unroll
        for (int nt = 0; nt < 4; ++nt) {
            int col = n0 + wn * 32 + nt * 8 + gc;
            float bx = bias ? bias[col] : 0.0f;
            float by = bias ? bias[col + 1] : 0.0f;
            float v0 = acc[mt][nt][0] + bx;
            float v1 = acc[mt][nt][1] + by;
            float v2 = acc[mt][nt][2] + bx;
            float v3 = acc[mt][nt][3] + by;
            if (res) {
                if (row < M) {
                    const float2 r0 = *(const float2*)(res + (size_t)row * N + col);
                    v0 += r0.x; v1 += r0.y;
                }
                if (row + 8 < M) {
                    const float2 r1 = *(const float2*)(res + (size_t)(row + 8) * N + col);
                    v2 += r1.x; v3 += r1.y;
                }
            }
            if (relu) {
                v0 = fmaxf(v0, 0.f); v1 = fmaxf(v1, 0.f);
                v2 = fmaxf(v2, 0.f); v3 = fmaxf(v3, 0.f);
            }
            if (Csplit) {
                auto sp = [&](int r, float a0, float a1) {
                    __nv_bfloat16 h0 = __float2bfloat16(a0);
                    __nv_bfloat16 l0 = __float2bfloat16(a0 - __bfloat162float(h0));
                    __nv_bfloat16 h1 = __float2bfloat16(a1);
                    __nv_bfloat16 l1 = __float2bfloat16(a1 - __bfloat162float(h1));
                    __nv_bfloat16* base = Csplit + (size_t)r * 3 * N;
                    __nv_bfloat162 hi2; hi2.x = h0; hi2.y = h1;
                    __nv_bfloat162 lo2; lo2.x = l0; lo2.y = l1;
                    *(__nv_bfloat162*)(base + col) = hi2;
                    *(__nv_bfloat162*)(base + N + col) = hi2;
                    *(__nv_bfloat162*)(base + 2 * N + col) = lo2;
                };
                if (row < M) sp(row, v0, v1);
                if (row + 8 < M) sp(row + 8, v2, v3);
            } else if (Cb) {
                if (row < M) {
                    __nv_bfloat162 o; o.x = __float2bfloat16(v0); o.y = __float2bfloat16(v1);
                    *(__nv_bfloat162*)(Cb + (size_t)row * N + col) = o;
                }
                if (row + 8 < M) {
                    __nv_bfloat162 o; o.x = __float2bfloat16(v2); o.y = __float2bfloat16(v3);
                    *(__nv_bfloat162*)(Cb + (size_t)(row + 8) * N + col) = o;
                }
            } else {
                if (row < M)
                    *(float2*)(Cf + (size_t)row * N + col) = make_float2(v0, v1);
                if (row + 8 < M)
                    *(float2*)(Cf + (size_t)(row + 8) * N + col) = make_float2(v2, v3);
            }
        }
    }
}

__global__ __launch_bounds__(256, 2) void mma_gemm_kernel(
    const __nv_bfloat16* __restrict__ A, int lda, int Kp,
    const __nv_bfloat16* __restrict__ B, int N,
    const float* __restrict__ bias, const float* __restrict__ res,
    float* Cf, __nv_bfloat16* Cb, __nv_bfloat16* Csplit, int M, int relu)
{
    extern __shared__ __align__(16) __nv_bfloat16 dsm[];
    gemm_core(dsm, dsm + 2 * STAGE_A, A, lda, Kp, B, N, bias, res,
              Cf, Cb, Csplit, M, relu, blockIdx.y * BM, blockIdx.x * BN);
}

__global__ __launch_bounds__(256, 2) void mma_qkv_kernel(
    const __nv_bfloat16* __restrict__ A, const float* __restrict__ x,
    const float* __restrict__ bq, const float* __restrict__ bk,
    const float* __restrict__ bv, const float* __restrict__ bs, int M)
{
    extern __shared__ __align__(16) __nv_bfloat16 dsm[];
    int bx = blockIdx.x;
    int m0 = blockIdx.y * BM;
    if (bx < 24) {
        int seg = bx >> 3;
        int n0 = (bx & 7) * BN;
        const __nv_bfloat16* B;
        const float* bias;
        __nv_bfloat16* Cb;
        if (seg == 0)      { B = d_B2q; bias = bq; Cb = d_qb; }
        else if (seg == 1) { B = d_B2k; bias = bk; Cb = d_kb; }
        else               { B = d_B2v; bias = bv; Cb = d_vb; }
        gemm_core(dsm, dsm + 2 * STAGE_A, A, 3 * DD, DD, B, HC, bias, nullptr,
                  nullptr, Cb, nullptr, M, 0, m0, n0);
    } else {
        // skip projection with x folded in: d_skip = x + x@Wskip + bskip
        gemm_core(dsm, dsm + 2 * STAGE_A, A, 3 * DD, 3 * DD, d_B2s, DD, bs,
                  x, d_skip, nullptr, nullptr, M, 0, m0, 0);
    }
}

__global__ __launch_bounds__(256, 2) void mma_ffn2sk_kernel(
    const __nv_bfloat16* __restrict__ A, int M)
{
    extern __shared__ __align__(16) __nv_bfloat16 dsm[];
    int ks = blockIdx.x;
    gemm_core(dsm, dsm + 2 * STAGE_A,
              A + ks * 384, 3 * FFD, 384,
              d_B2w2 + (size_t)ks * 384 * DD, DD,
              nullptr, nullptr,
              d_part + (size_t)ks * NN * DD, nullptr, nullptr,
              M, 0, blockIdx.y * BM, 0);
}

// reduce 4 partials + bias + residual(h) + LN2 -> out; re-zero deg/cur
__global__ __launch_bounds__(256) void ln2_reduce_kernel(
    const float* __restrict__ b2, const float* __restrict__ g2,
    const float* __restrict__ beta2, float* __restrict__ out)
{
    int gt = blockIdx.x * blockDim.x + threadIdx.x;
    if (gt < NN) { d_deg[gt] = 0; d_cur[gt] = 0; }   // reset for next replay
    int row = gt >> 5;
    int lane = gt & 31;
    if (row >= NN) return;
    size_t ro = (size_t)row * DD;
    float4 v = ((const float4*)(d_part + ro))[lane];
    float4 p1 = ((const float4*)(d_part + NN * DD + ro))[lane];
    float4 p2 = ((const float4*)(d_part + 2 * NN * DD + ro))[lane];
    float4 p3 = ((const float4*)(d_part + 3 * NN * DD + ro))[lane];
    float4 hres = ((const float4*)(d_h + ro))[lane];
    float4 bb2 = ((const float4*)b2)[lane];
    v.x = ((v.x + p1.x) + (p2.x + p3.x)) + bb2.x + hres.x;
    v.y = ((v.y + p1.y) + (p2.y + p3.y)) + bb2.y + hres.y;
    v.z = ((v.z + p1.z) + (p2.z + p3.z)) + bb2.z + hres.z;
    v.w = ((v.w + p1.w) + (p2.w + p3.w)) + bb2.w + hres.w;
    float s = v.x + v.y + v.z + v.w;
    float qq = v.x * v.x + v.y * v.y + v.z * v.z + v.w * v.w;
#pragma unroll
    for (int ofs = 16; ofs > 0; ofs >>= 1) {
        s  += __shfl_xor_sync(0xffffffffu, s, ofs);
        qq += __shfl_xor_sync(0xffffffffu, qq, ofs);
    }
    float mean = s * (1.0f / 128.0f);
    float var = qq * (1.0f / 128.0f) - mean * mean;
    float rs = rsqrtf(var + 1e-5f);
    float4 gg = ((const float4*)g2)[lane];
    float4 bb = ((const float4*)beta2)[lane];
    float4 o;
    o.x = (v.x - mean) * rs * gg.x + bb.x;
    o.y = (v.y - mean) * rs * gg.y + bb.y;
    o.z = (v.z - mean) * rs * gg.z + bb.z;
    o.w = (v.w - mean) * rs * gg.w + bb.w;
    ((float4*)(out + ro))[lane] = o;
}

// ---------------- attention + residual(+x in skip) + fused LN1 --------------
__device__ __forceinline__ float4 cvt4(uint2 u) {
    __nv_bfloat162 lo = *reinterpret_cast<__nv_bfloat162*>(&u.x);
    __nv_bfloat162 hi = *reinterpret_cast<__nv_bfloat162*>(&u.y);
    float2 a = __bfloat1622float2(lo);
    float2 b = __bfloat1622float2(hi);
    return make_float4(a.x, a.y, b.x, b.y);
}

__global__ __launch_bounds__(128) void attn_kernel(const float* __restrict__ g1,
                                                   const float* __restrict__ beta1)
{
    int gw = (blockIdx.x * blockDim.x + threadIdx.x) >> 5;
    int lane = threadIdx.x & 31;
    if (gw >= NN) return;

    const uint2* qrow = (const uint2*)(d_qb + (size_t)gw * HC);
    float4 q[8];
#pragma unroll
    for (int j = 0; j < 8; ++j) q[j] = cvt4(qrow[j * 32 + lane]);

    float den[8];
    float4 acc[8];
#pragma unroll
    for (int j = 0; j < 8; ++j) {
        den[j] = 0.f;
        acc[j] = make_float4(0.f, 0.f, 0.f, 0.f);
    }

    int s0 = d_off[gw], s1 = d_off[gw + 1];
    const float scale = 0.08838834764831845f;  // 1/sqrt(128)
    const bool b16 = (lane & 16) != 0;
    const bool b8  = (lane & 8) != 0;
    const bool b4  = (lane & 4) != 0;

#pragma unroll 2
    for (int s = s0; s < s1; ++s) {
        int src = d_ssrc[s];
        const uint2* kr = (const uint2*)(d_kb + (size_t)src * HC);
        const uint2* vr = (const uint2*)(d_vb + (size_t)src * HC);
        float p[8];
#pragma unroll
        for (int j = 0; j < 8; ++j) {
            float4 kk = cvt4(kr[j * 32 + lane]);
            p[j] = q[j].x * kk.x + q[j].y * kk.y + q[j].z * kk.z + q[j].w * kk.w;
        }
        float s4[4];
#pragma unroll
        for (int i = 0; i < 4; ++i) {
            float snd = b16 ? p[i] : p[i + 4];
            float rcv = __shfl_xor_sync(0xffffffffu, snd, 16);
            s4[i] = (b16 ? p[i + 4] : p[i]) + rcv;
        }
        float s2[2];
#pragma unroll
        for (int i = 0; i < 2; ++i) {
            float snd = b8 ? s4[i] : s4[i + 2];
            float rcv = __shfl_xor_sync(0xffffffffu, snd, 8);
            s2[i] = (b8 ? s4[i + 2] : s4[i]) + rcv;
        }
        {
            float snd = b4 ? s2[0] : s2[1];
            float rcv = __shfl_xor_sync(0xffffffffu, snd, 4);
            float t = (b4 ? s2[1] : s2[0]) + rcv;
            t += __shfl_xor_sync(0xffffffffu, t, 2);
            t += __shfl_xor_sync(0xffffffffu, t, 1);
            float wself = __expf(t * scale);
            float w[8];
#pragma unroll
            for (int j = 0; j < 8; ++j)
                w[j] = __shfl_sync(0xffffffffu, wself, j * 4);
#pragma unroll
            for (int j = 0; j < 8; ++j) {
                float4 vv = cvt4(vr[j * 32 + lane]);
                acc[j].x += w[j] * vv.x;
                acc[j].y += w[j] * vv.y;
                acc[j].z += w[j] * vv.z;
                acc[j].w += w[j] * vv.w;
                den[j] += w[j];
            }
        }
    }

    float4 r = make_float4(0.f, 0.f, 0.f, 0.f);
#pragma unroll
    for (int j = 0; j < 8; ++j) {
        float inv = 1.0f / (den[j] + 1e-16f);
        r.x += acc[j].x * inv;
        r.y += acc[j].y * inv;
        r.z += acc[j].z * inv;
        r.w += acc[j].w * inv;
    }
    r.x *= 0.125f; r.y *= 0.125f; r.z *= 0.125f; r.w *= 0.125f;

    // d_skip already holds x + x@Wskip + bskip
    float4 sk = ((const float4*)(d_skip + (size_t)gw * DD))[lane];
    float4 o = make_float4(sk.x + r.x, sk.y + r.y, sk.z + r.z, sk.w + r.w);

    float s = o.x + o.y + o.z + o.w;
    float qq = o.x * o.x + o.y * o.y + o.z * o.z + o.w * o.w;
#pragma unroll
    for (int ofs = 16; ofs > 0; ofs >>= 1) {
        s  += __shfl_xor_sync(0xffffffffu, s, ofs);
        qq += __shfl_xor_sync(0xffffffffu, qq, ofs);
    }
    float mean = s * (1.0f / 128.0f);
    float var = qq * (1.0f / 128.0f) - mean * mean;
    float rs = rsqrtf(var + 1e-5f);
    float4 gg = ((const float4*)g1)[lane];
    float4 bb = ((const float4*)beta1)[lane];
    float4 hv;
    hv.x = (o.x - mean) * rs * gg.x + bb.x;
    hv.y = (o.y - mean) * rs * gg.y + bb.y;
    hv.z = (o.z - mean) * rs * gg.z + bb.z;
    hv.w = (o.w - mean) * rs * gg.w + bb.w;
    ((float4*)(d_h + (size_t)gw * DD))[lane] = hv;

    __nv_bfloat16* base = d_A2h + (size_t)gw * 3 * DD + lane * 4;
    float vals[4] = {hv.x, hv.y, hv.z, hv.w};
    __nv_bfloat162 hi2[2], lo2[2];
#pragma unroll
    for (int i = 0; i < 2; ++i) {
        __nv_bfloat16 h0 = __float2bfloat16(vals[2 * i]);
        __nv_bfloat16 h1 = __float2bfloat16(vals[2 * i + 1]);
        __nv_bfloat16 l0 = __float2bfloat16(vals[2 * i] - __bfloat162float(h0));
        __nv_bfloat16 l1 = __float2bfloat16(vals[2 * i + 1] - __bfloat162float(h1));
        hi2[i].x = h0; hi2[i].y = h1;
        lo2[i].x = l0; lo2[i].y = l1;
    }
    *(__nv_bfloat162*)(base) = hi2[0];
    *(__nv_bfloat162*)(base + 2) = hi2[1];
    *(__nv_bfloat162*)(base + DD) = hi2[0];
    *(__nv_bfloat162*)(base + DD + 2) = hi2[1];
    *(__nv_bfloat162*)(base + 2 * DD) = lo2[0];
    *(__nv_bfloat162*)(base + 2 * DD + 2) = lo2[1];
}

// ---------------- launcher --------------------------------------------------
extern "C" void kernel_launch(void* const* d_in, const int* in_sizes, int n_in,
                              void* d_out, int out_size)
{
    const float* x     = (const float*)d_in[0];
    const void*  ei    = d_in[1];
    const float* Wq    = (const float*)d_in[2];
    const float* bq    = (const float*)d_in[3];
    const float* Wk    = (const float*)d_in[4];
    const float* bk    = (const float*)d_in[5];
    const float* Wv    = (const float*)d_in[6];
    const float* bv    = (const float*)d_in[7];
    const float* Wskip = (const float*)d_in[8];
    const float* bskip = (const float*)d_in[9];
    const float* g1    = (const float*)d_in[10];
    const float* beta1 = (const float*)d_in[11];
    const float* W1    = (const float*)d_in[12];
    const float* b1    = (const float*)d_in[13];
    const float* W2    = (const float*)d_in[14];
    const float* b2    = (const float*)d_in[15];
    const float* g2    = (const float*)d_in[16];
    const float* beta2 = (const float*)d_in[17];
    float* out = (float*)d_out;

    void *pA2x, *pA2h, *pA2f, *pB2w1;
    cudaGetSymbolAddress(&pA2x, d_A2x);
    cudaGetSymbolAddress(&pA2h, d_A2h);
    cudaGetSymbolAddress(&pA2f, d_A2f);
    cudaGetSymbolAddress(&pB2w1, d_B2w1);

    static cudaStream_t s_side = nullptr;
    static cudaEvent_t s_fork = nullptr, s_join = nullptr;
    if (s_side == nullptr) {
        cudaStreamCreateWithFlags(&s_side, cudaStreamNonBlocking);
        cudaEventCreateWithFlags(&s_fork, cudaEventDisableTiming);
        cudaEventCreateWithFlags(&s_join, cudaEventDisableTiming);
        cudaFuncSetAttribute(mma_gemm_kernel,
                             cudaFuncAttributeMaxDynamicSharedMemorySize,
                             GEMM_SMEM_BYTES);
        cudaFuncSetAttribute(mma_qkv_kernel,
                             cudaFuncAttributeMaxDynamicSharedMemorySize,
                             GEMM_SMEM_BYTES);
        cudaFuncSetAttribute(mma_ffn2sk_kernel,
                             cudaFuncAttributeMaxDynamicSharedMemorySize,
                             GEMM_SMEM_BYTES);
    }

    const int MT = (NN + BM - 1) / BM;  // 79

    // fork: CSR chain + W1/W2 splits on side stream
    cudaEventRecord(s_fork, 0);
    cudaStreamWaitEvent(s_side, s_fork, 0);
    detect_kernel<<<1, 32, 0, s_side>>>(ei);
    hist_kernel<<<(EE + 255) / 256, 256, 0, s_side>>>(ei);
    scan_kernel<<<1, 1024, 0, s_side>>>();
    scatter_kernel<<<(EE + 255) / 256, 256, 0, s_side>>>(ei);
    splitSide_kernel<<<(SPLIT_SIDE + 255) / 256, 256, 0, s_side>>>(W1, W2);
    cudaEventRecord(s_join, s_side);

    // main stream
    splitMain_kernel<<<(SPLIT_MAIN + 255) / 256, 256>>>(x, Wq, Wk, Wv, Wskip);
    mma_qkv_kernel<<<dim3(25, MT), 256, GEMM_SMEM_BYTES>>>(
        (const __nv_bfloat16*)pA2x, x, bq, bk, bv, bskip, NN);

    cudaStreamWaitEvent(0, s_join, 0);

    attn_kernel<<<(NN * 32 + 127) / 128, 128>>>(g1, beta1);

    mma_gemm_kernel<<<dim3(FFD / BN, MT), 256, GEMM_SMEM_BYTES>>>(
        (const __nv_bfloat16*)pA2h, 3 * DD, 3 * DD, (const __nv_bfloat16*)pB2w1,
        FFD, b1, nullptr, nullptr, nullptr, (__nv_bfloat16*)pA2f, NN, 1);

    mma_ffn2sk_kernel<<<dim3(4, MT), 256, GEMM_SMEM_BYTES>>>(
        (const __nv_bfloat16*)pA2f, NN);

    ln2_reduce_kernel<<<(NN * 32 + 255) / 256, 256>>>(b2, g2, beta2, out);
}

// round 16
// speedup vs baseline: 1.0069x; 1.0069x over previous
#include <cuda_runtime.h>
#include <cuda_bf16.h>
#include <cstdint>

#define NN 10000
#define EE 160000
#define DD 128
#define HH 8
#define HC 1024
#define FFD 512

// ---------------- scratch ----------------------------------------------------
static __device__ __align__(16) __nv_bfloat16 d_qb[NN * HC];
static __device__ __align__(16) __nv_bfloat16 d_kb[NN * HC];
static __device__ __align__(16) __nv_bfloat16 d_vb[NN * HC];
static __device__ __align__(16) float d_skip[NN * DD];   // holds x + x@Wskip + bskip
static __device__ __align__(16) float d_h[NN * DD];
static __device__ __align__(16) float d_part[4 * NN * DD];   // FFN2 split-K partials
static __device__ int d_deg[NN];
static __device__ int d_off[NN + 1];
static __device__ int d_cur[NN];
static __device__ int d_ssrc[EE];
static __device__ int d_is64;

// bf16 split buffers (A' = [hi|hi|lo] along K, B' = [hi;lo;hi] along K)
static __device__ __align__(16) __nv_bfloat16 d_A2x[NN * 3 * DD];
static __device__ __align__(16) __nv_bfloat16 d_A2h[NN * 3 * DD];
static __device__ __align__(16) __nv_bfloat16 d_A2f[NN * 3 * FFD];
static __device__ __align__(16) __nv_bfloat16 d_B2q[3 * DD * HC];
static __device__ __align__(16) __nv_bfloat16 d_B2k[3 * DD * HC];
static __device__ __align__(16) __nv_bfloat16 d_B2v[3 * DD * HC];
static __device__ __align__(16) __nv_bfloat16 d_B2s[3 * DD * DD];
static __device__ __align__(16) __nv_bfloat16 d_B2w1[3 * DD * FFD];
static __device__ __align__(16) __nv_bfloat16 d_B2w2[3 * FFD * DD];

// ---------------- edge dtype detect ------------------------------------------
__global__ void detect_kernel(const void* ei) {
    if (blockIdx.x == 0 && threadIdx.x == 0) {
        const unsigned int* w = (const unsigned int*)ei;
        int is64 = 1;
        for (int j = 0; j < 64; ++j) {
            if (w[2 * j + 1] != 0u) { is64 = 0; break; }
        }
        d_is64 = is64;
    }
}

__device__ __forceinline__ int edge_val(const void* ei, int idx) {
    return d_is64 ? (int)((const long long*)ei)[idx] : ((const int*)ei)[idx];
}

// d_deg / d_cur zeroed statically on first use, re-zeroed in ln2_reduce.
__global__ void hist_kernel(const void* __restrict__ ei) {
    int e = blockIdx.x * blockDim.x + threadIdx.x;
    if (e >= EE) return;
    atomicAdd(&d_deg[edge_val(ei, EE + e)], 1);
}

__global__ void scan_kernel() {
    __shared__ int sm[1024];
    int t = threadIdx.x;
    int base = t * 10;
    int loc[10];
    int run = 0;
#pragma unroll
    for (int j = 0; j < 10; ++j) {
        int idx = base + j;
        loc[j] = run;
        run += (idx < NN) ? d_deg[idx] : 0;
    }
    sm[t] = run;
    __syncthreads();
    for (int ofs = 1; ofs < 1024; ofs <<= 1) {
        int v = (t >= ofs) ? sm[t - ofs] : 0;
        __syncthreads();
        sm[t] += v;
        __syncthreads();
    }
    int pre = (t == 0) ? 0 : sm[t - 1];
#pragma unroll
    for (int j = 0; j < 10; ++j) {
        int idx = base + j;
        if (idx < NN) d_off[idx] = pre + loc[j];
    }
    if (t == 1023) d_off[NN] = sm[1023];
}

__global__ void scatter_kernel(const void* __restrict__ ei) {
    int e = blockIdx.x * blockDim.x + threadIdx.x;
    if (e >= EE) return;
    int src = edge_val(ei, e);
    int dst = edge_val(ei, EE + e);
    int pos = atomicAdd(&d_cur[dst], 1);
    d_ssrc[d_off[dst] + pos] = src;
}

// ---------------- splits -----------------------------------------------------
#define SZX   (NN * DD)
#define SZQKV (DD * HC)
#define SZS   (DD * DD)
#define SZW1  (DD * FFD)
#define SZW2  (FFD * DD)
#define SPLIT_MAIN (SZX + 3 * SZQKV + SZS)
#define SPLIT_SIDE (SZW1 + SZW2)

__device__ __forceinline__ void put_splitB(const float* in, __nv_bfloat16* out,
                                           int idx, int K, int N) {
    int k = idx / N, n = idx - k * N;
    float a = in[idx];
    __nv_bfloat16 hi = __float2bfloat16(a);
    __nv_bfloat16 lo = __float2bfloat16(a - __bfloat162float(hi));
    out[(size_t)k * N + n] = hi;
    out[(size_t)(K + k) * N + n] = lo;
    out[(size_t)(2 * K + k) * N + n] = hi;
}

__global__ void splitMain_kernel(const float* x, const float* Wq,
                                 const float* Wk, const float* Wv,
                                 const float* Ws)
{
    int i = blockIdx.x * blockDim.x + threadIdx.x;
    if (i >= SPLIT_MAIN) return;
    if (i < SZX) {
        int m = i / DD, k = i - m * DD;
        float a = x[i];
        __nv_bfloat16 hi = __float2bfloat16(a);
        __nv_bfloat16 lo = __float2bfloat16(a - __bfloat162float(hi));
        __nv_bfloat16* o = d_A2x + (size_t)m * 3 * DD;
        o[k] = hi;
        o[DD + k] = hi;
        o[2 * DD + k] = lo;
        return;
    }
    int j = i - SZX;
    if (j < SZQKV)          put_splitB(Wq, d_B2q, j, DD, HC);
    else if (j < 2 * SZQKV) put_splitB(Wk, d_B2k, j - SZQKV, DD, HC);
    else if (j < 3 * SZQKV) put_splitB(Wv, d_B2v, j - 2 * SZQKV, DD, HC);
    else                    put_splitB(Ws, d_B2s, j - 3 * SZQKV, DD, DD);
}

__global__ void splitSide_kernel(const float* W1, const float* W2) {
    int i = blockIdx.x * blockDim.x + threadIdx.x;
    if (i >= SPLIT_SIDE) return;
    if (i < SZW1) put_splitB(W1, d_B2w1, i, DD, FFD);
    else          put_splitB(W2, d_B2w2, i - SZW1, FFD, DD);
}

// ---------------- bf16 tensor-core GEMM core (BK=64, 2-stage) ----------------
#define BM 128
#define BN 128
#define BK 64
#define ASTRIDE 72            // BK + 8
#define BSTRIDE 136           // BN + 8
#define STAGE_A (BM * ASTRIDE)    // 9216 bf16
#define STAGE_B (BK * BSTRIDE)    // 8704 bf16
#define GEMM_SMEM_BYTES (2 * (STAGE_A + STAGE_B) * 2)   // 71680 B

__device__ __forceinline__ uint32_t smem_u32(const void* p) {
    return (uint32_t)__cvta_generic_to_shared(p);
}

__device__ __forceinline__ void ldmatrix_x4(uint32_t& r0, uint32_t& r1,
                                            uint32_t& r2, uint32_t& r3,
                                            uint32_t addr) {
    asm volatile("ldmatrix.sync.aligned.m8n8.x4.shared.b16 {%0,%1,%2,%3}, [%4];"
                 : "=r"(r0), "=r"(r1), "=r"(r2), "=r"(r3) : "r"(addr));
}

__device__ __forceinline__ void ldmatrix_x4_trans(uint32_t& r0, uint32_t& r1,
                                                  uint32_t& r2, uint32_t& r3,
                                                  uint32_t addr) {
    asm volatile("ldmatrix.sync.aligned.m8n8.x4.trans.shared.b16 {%0,%1,%2,%3}, [%4];"
                 : "=r"(r0), "=r"(r1), "=r"(r2), "=r"(r3) : "r"(addr));
}

__device__ __forceinline__ void mma_bf16(float& c0, float& c1, float& c2, float& c3,
                                         uint32_t a0, uint32_t a1, uint32_t a2,
                                         uint32_t a3, uint32_t b0, uint32_t b1) {
    asm volatile(
        "mma.sync.aligned.m16n8k16.row.col.f32.bf16.bf16.f32 "
        "{%0,%1,%2,%3}, {%4,%5,%6,%7}, {%8,%9}, {%0,%1,%2,%3};"
        : "+f"(c0), "+f"(c1), "+f"(c2), "+f"(c3)
        : "r"(a0), "r"(a1), "r"(a2), "r"(a3), "r"(b0), "r"(b1));
}

__device__ __forceinline__ void cp_async16(uint32_t saddr, const void* gaddr,
                                           int src_sz) {
    asm volatile("cp.async.cg.shared.global [%0], [%1], 16, %2;"
                 :: "r"(saddr), "l"(gaddr), "r"(src_sz));
}

__device__ __forceinline__ void gemm_core(
    __nv_bfloat16* As, __nv_bfloat16* Bs,
    const __nv_bfloat16* __restrict__ A, int lda, int Kp,
    const __nv_bfloat16* __restrict__ B, int N,
    const float* __restrict__ bias, const float* __restrict__ res,
    float* Cf, __nv_bfloat16* Cb, __nv_bfloat16* Csplit,
    int M, int relu, int m0, int n0)
{
    int tid = threadIdx.x;
    int lane = tid & 31;
    int wid = tid >> 5;
    int wm = wid >> 2;
    int wn = wid & 3;

    float acc[4][4][4];
#pragma unroll
    for (int i = 0; i < 4; ++i)
#pragma unroll
        for (int j = 0; j < 4; ++j)
#pragma unroll
            for (int c = 0; c < 4; ++c) acc[i][j][c] = 0.0f;

    const int T = Kp / BK;

    auto load_stage = [&](int t, int buf) {
        int ko = t * BK;
        __nv_bfloat16* as = As + buf * STAGE_A;
        __nv_bfloat16* bs = Bs + buf * STAGE_B;
#pragma unroll
        for (int i = 0; i < 4; ++i) {
            int c = tid + i * 256;
            int row = c >> 3;
            int col = (c & 7) * 8;
            int gm = m0 + row;
            uint32_t s = smem_u32(as + row * ASTRIDE + col);
            const void* g = A + (size_t)gm * lda + ko + col;
            cp_async16(s, g, gm < M ? 16 : 0);
        }
#pragma unroll
        for (int i = 0; i < 4; ++i) {
            int c = tid + i * 256;
            int row = c >> 4;
            int col = (c & 15) * 8;
            uint32_t s = smem_u32(bs + row * BSTRIDE + col);
            const void* g = B + (size_t)(ko + row) * N + n0 + col;
            cp_async16(s, g, 16);
        }
        asm volatile("cp.async.commit_group;");
    };

    load_stage(0, 0);

    for (int t = 0; t < T; ++t) {
        if (t + 1 < T) {
            load_stage(t + 1, (t + 1) & 1);
            asm volatile("cp.async.wait_group 1;");
        } else {
            asm volatile("cp.async.wait_group 0;");
        }
        __syncthreads();

        int buf = t & 1;
        const __nv_bfloat16* as = As + buf * STAGE_A;
        const __nv_bfloat16* bs = Bs + buf * STAGE_B;
#pragma unroll
        for (int ks = 0; ks < 4; ++ks) {
            uint32_t a[4][4];
#pragma unroll
            for (int mt = 0; mt < 4; ++mt) {
                int row = wm * 64 + mt * 16 + (lane & 15);
                int col = ks * 16 + ((lane >> 4) << 3);
                ldmatrix_x4(a[mt][0], a[mt][1], a[mt][2], a[mt][3],
                            smem_u32(as + row * ASTRIDE + col));
            }
            uint32_t b[2][4];
#pragma unroll
            for (int n16 = 0; n16 < 2; ++n16) {
                int row = ks * 16 + (lane & 15);
                int col = wn * 32 + n16 * 16 + ((lane >> 4) << 3);
                ldmatrix_x4_trans(b[n16][0], b[n16][1], b[n16][2], b[n16][3],
                                  smem_u32(bs + row * BSTRIDE + col));
            }
#pragma unroll
            for (int mt = 0; mt < 4; ++mt)
#pragma unroll
                for (int nt = 0; nt < 4; ++nt) {
                    mma_bf16(acc[mt][nt][0], acc[mt][nt][1],
                             acc[mt][nt][2], acc[mt][nt][3],
                             a[mt][0], a[mt][1], a[mt][2], a[mt][3],
                             b[nt >> 1][(nt & 1) * 2],
                             b[nt >> 1][(nt & 1) * 2 + 1]);
                }
        }
        __syncthreads();
    }

    int gr = lane >> 2;
    int gc = (lane & 3) * 2;
#pragma unroll
    for (int mt = 0; mt < 4; ++mt) {
        int row = m0 + wm * 64 + mt * 16 + gr;
#pragma unroll
        for (int nt = 0; nt < 4; ++nt) {
            int col = n0 + wn * 32 + nt * 8 + gc;
            float bx = bias ? bias[col] : 0.0f;
            float by = bias ? bias[col + 1] : 0.0f;
            float v0 = acc[mt][nt][0] + bx;
            float v1 = acc[mt][nt][1] + by;
            float v2 = acc[mt][nt][2] + bx;
            float v3 = acc[mt][nt][3] + by;
            if (res) {
                if (row < M) {
                    const float2 r0 = *(const float2*)(res + (size_t)row * N + col);
                    v0 += r0.x; v1 += r0.y;
                }
                if (row + 8 < M) {
                    const float2 r1 = *(const float2*)(res + (size_t)(row + 8) * N + col);
                    v2 += r1.x; v3 += r1.y;
                }
            }
            if (relu) {
                v0 = fmaxf(v0, 0.f); v1 = fmaxf(v1, 0.f);
                v2 = fmaxf(v2, 0.f); v3 = fmaxf(v3, 0.f);
            }
            if (Csplit) {
                auto sp = [&](int r, float a0, float a1) {
                    __nv_bfloat16 h0 = __float2bfloat16(a0);
                    __nv_bfloat16 l0 = __float2bfloat16(a0 - __bfloat162float(h0));
                    __nv_bfloat16 h1 = __float2bfloat16(a1);
                    __nv_bfloat16 l1 = __float2bfloat16(a1 - __bfloat162float(h1));
                    __nv_bfloat16* base = Csplit + (size_t)r * 3 * N;
                    __nv_bfloat162 hi2; hi2.x = h0; hi2.y = h1;
                    __nv_bfloat162 lo2; lo2.x = l0; lo2.y = l1;
                    *(__nv_bfloat162*)(base + col) = hi2;
                    *(__nv_bfloat162*)(base + N + col) = hi2;
                    *(__nv_bfloat162*)(base + 2 * N + col) = lo2;
                };
                if (row < M) sp(row, v0, v1);
                if (row + 8 < M) sp(row + 8, v2, v3);
            } else if (Cb) {
                if (row < M) {
                    __nv_bfloat162 o; o.x = __float2bfloat16(v0); o.y = __float2bfloat16(v1);
                    *(__nv_bfloat162*)(Cb + (size_t)row * N + col) = o;
                }
                if (row + 8 < M) {
                    __nv_bfloat162 o; o.x = __float2bfloat16(v2); o.y = __float2bfloat16(v3);
                    *(__nv_bfloat162*)(Cb + (size_t)(row + 8) * N + col) = o;
                }
            } else {
                if (row < M)
                    *(float2*)(Cf + (size_t)row * N + col) = make_float2(v0, v1);
                if (row + 8 < M)
                    *(float2*)(Cf + (size_t)(row + 8) * N + col) = make_float2(v2, v3);
            }
        }
    }
}

__global__ __launch_bounds__(256, 2) void mma_gemm_kernel(
    const __nv_bfloat16* __restrict__ A, int lda, int Kp,
    const __nv_bfloat16* __restrict__ B, int N,
    const float* __restrict__ bias, const float* __restrict__ res,
    float* Cf, __nv_bfloat16* Cb, __nv_bfloat16* Csplit, int M, int relu)
{
    extern __shared__ __align__(16) __nv_bfloat16 dsm[];
    gemm_core(dsm, dsm + 2 * STAGE_A, A, lda, Kp, B, N, bias, res,
              Cf, Cb, Csplit, M, relu, blockIdx.y * BM, blockIdx.x * BN);
}

__global__ __launch_bounds__(256, 2) void mma_qkv_kernel(
    const __nv_bfloat16* __restrict__ A, const float* __restrict__ x,
    const float* __restrict__ bq, const float* __restrict__ bk,
    const float* __restrict__ bv, const float* __restrict__ bs, int M)
{
    extern __shared__ __align__(16) __nv_bfloat16 dsm[];
    int bx = blockIdx.x;
    int m0 = blockIdx.y * BM;
    if (bx < 24) {
        int seg = bx >> 3;
        int n0 = (bx & 7) * BN;
        const __nv_bfloat16* B;
        const float* bias;
        __nv_bfloat16* Cb;
        if (seg == 0)      { B = d_B2q; bias = bq; Cb = d_qb; }
        else if (seg == 1) { B = d_B2k; bias = bk; Cb = d_kb; }
        else               { B = d_B2v; bias = bv; Cb = d_vb; }
        gemm_core(dsm, dsm + 2 * STAGE_A, A, 3 * DD, DD, B, HC, bias, nullptr,
                  nullptr, Cb, nullptr, M, 0, m0, n0);
    } else {
        // skip projection with x folded in: d_skip = x + x@Wskip + bskip
        gemm_core(dsm, dsm + 2 * STAGE_A, A, 3 * DD, 3 * DD, d_B2s, DD, bs,
                  x, d_skip, nullptr, nullptr, M, 0, m0, 0);
    }
}

__global__ __launch_bounds__(256, 2) void mma_ffn2sk_kernel(
    const __nv_bfloat16* __restrict__ A, int M)
{
    extern __shared__ __align__(16) __nv_bfloat16 dsm[];
    int ks = blockIdx.x;
    gemm_core(dsm, dsm + 2 * STAGE_A,
              A + ks * 384, 3 * FFD, 384,
              d_B2w2 + (size_t)ks * 384 * DD, DD,
              nullptr, nullptr,
              d_part + (size_t)ks * NN * DD, nullptr, nullptr,
              M, 0, blockIdx.y * BM, 0);
}

// reduce 4 partials + bias + residual(h) + LN2 -> out; re-zero deg/cur
__global__ __launch_bounds__(256) void ln2_reduce_kernel(
    const float* __restrict__ b2, const float* __restrict__ g2,
    const float* __restrict__ beta2, float* __restrict__ out)
{
    int gt = blockIdx.x * blockDim.x + threadIdx.x;
    if (gt < NN) { d_deg[gt] = 0; d_cur[gt] = 0; }   // reset for next replay
    int row = gt >> 5;
    int lane = gt & 31;
    if (row >= NN) return;
    size_t ro = (size_t)row * DD;
    float4 v = ((const float4*)(d_part + ro))[lane];
    float4 p1 = ((const float4*)(d_part + NN * DD + ro))[lane];
    float4 p2 = ((const float4*)(d_part + 2 * NN * DD + ro))[lane];
    float4 p3 = ((const float4*)(d_part + 3 * NN * DD + ro))[lane];
    float4 hres = ((const float4*)(d_h + ro))[lane];
    float4 bb2 = ((const float4*)b2)[lane];
    v.x = ((v.x + p1.x) + (p2.x + p3.x)) + bb2.x + hres.x;
    v.y = ((v.y + p1.y) + (p2.y + p3.y)) + bb2.y + hres.y;
    v.z = ((v.z + p1.z) + (p2.z + p3.z)) + bb2.z + hres.z;
    v.w = ((v.w + p1.w) + (p2.w + p3.w)) + bb2.w + hres.w;
    float s = v.x + v.y + v.z + v.w;
    float qq = v.x * v.x + v.y * v.y + v.z * v.z + v.w * v.w;
#pragma unroll
    for (int ofs = 16; ofs > 0; ofs >>= 1) {
        s  += __shfl_xor_sync(0xffffffffu, s, ofs);
        qq += __shfl_xor_sync(0xffffffffu, qq, ofs);
    }
    float mean = s * (1.0f / 128.0f);
    float var = qq * (1.0f / 128.0f) - mean * mean;
    float rs = rsqrtf(var + 1e-5f);
    float4 gg = ((const float4*)g2)[lane];
    float4 bb = ((const float4*)beta2)[lane];
    float4 o;
    o.x = (v.x - mean) * rs * gg.x + bb.x;
    o.y = (v.y - mean) * rs * gg.y + bb.y;
    o.z = (v.z - mean) * rs * gg.z + bb.z;
    o.w = (v.w - mean) * rs * gg.w + bb.w;
    ((float4*)(out + ro))[lane] = o;
}

// ---------------- attention + residual(+x in skip) + fused LN1 --------------
__device__ __forceinline__ float4 cvt4(uint2 u) {
    __nv_bfloat162 lo = *reinterpret_cast<__nv_bfloat162*>(&u.x);
    __nv_bfloat162 hi = *reinterpret_cast<__nv_bfloat162*>(&u.y);
    float2 a = __bfloat1622float2(lo);
    float2 b = __bfloat1622float2(hi);
    return make_float4(a.x, a.y, b.x, b.y);
}

__global__ __launch_bounds__(128) void attn_kernel(const float* __restrict__ g1,
                                                   const float* __restrict__ beta1)
{
    int gw = (blockIdx.x * blockDim.x + threadIdx.x) >> 5;
    int lane = threadIdx.x & 31;
    if (gw >= NN) return;

    const uint2* qrow = (const uint2*)(d_qb + (size_t)gw * HC);
    float4 q[8];
#pragma unroll
    for (int j = 0; j < 8; ++j) q[j] = cvt4(qrow[j * 32 + lane]);

    float den[8];
    float4 acc[8];
#pragma unroll
    for (int j = 0; j < 8; ++j) {
        den[j] = 0.f;
        acc[j] = make_float4(0.f, 0.f, 0.f, 0.f);
    }

    int s0 = d_off[gw], s1 = d_off[gw + 1];
    const float scale = 0.08838834764831845f;  // 1/sqrt(128)
    const bool b16 = (lane & 16) != 0;
    const bool b8  = (lane & 8) != 0;
    const bool b4  = (lane & 4) != 0;

#pragma unroll 2
    for (int s = s0; s < s1; ++s) {
        int src = d_ssrc[s];
        const uint2* kr = (const uint2*)(d_kb + (size_t)src * HC);
        const uint2* vr = (const uint2*)(d_vb + (size_t)src * HC);
        float p[8];
#pragma unroll
        for (int j = 0; j < 8; ++j) {
            float4 kk = cvt4(kr[j * 32 + lane]);
            p[j] = q[j].x * kk.x + q[j].y * kk.y + q[j].z * kk.z + q[j].w * kk.w;
        }
        float s4[4];
#pragma unroll
        for (int i = 0; i < 4; ++i) {
            float snd = b16 ? p[i] : p[i + 4];
            float rcv = __shfl_xor_sync(0xffffffffu, snd, 16);
            s4[i] = (b16 ? p[i + 4] : p[i]) + rcv;
        }
        float s2[2];
#pragma unroll
        for (int i = 0; i < 2; ++i) {
            float snd = b8 ? s4[i] : s4[i + 2];
            float rcv = __shfl_xor_sync(0xffffffffu, snd, 8);
            s2[i] = (b8 ? s4[i + 2] : s4[i]) + rcv;
        }
        {
            float snd = b4 ? s2[0] : s2[1];
            float rcv = __shfl_xor_sync(0xffffffffu, snd, 4);
            float t = (b4 ? s2[1] : s2[0]) + rcv;
            t += __shfl_xor_sync(0xffffffffu, t, 2);
            t += __shfl_xor_sync(0xffffffffu, t, 1);
            float wself = __expf(t * scale);
            float w[8];
#pragma unroll
            for (int j = 0; j < 8; ++j)
                w[j] = __shfl_sync(0xffffffffu, wself, j * 4);
#pragma unroll
            for (int j = 0; j < 8; ++j) {
                float4 vv = cvt4(vr[j * 32 + lane]);
                acc[j].x += w[j] * vv.x;
                acc[j].y += w[j] * vv.y;
                acc[j].z += w[j] * vv.z;
                acc[j].w += w[j] * vv.w;
                den[j] += w[j];
            }
        }
    }

    float4 r = make_float4(0.f, 0.f, 0.f, 0.f);
#pragma unroll
    for (int j = 0; j < 8; ++j) {
        float inv = 1.0f / (den[j] + 1e-16f);
        r.x += acc[j].x * inv;
        r.y += acc[j].y * inv;
        r.z += acc[j].z * inv;
        r.w += acc[j].w * inv;
    }
    r.x *= 0.125f; r.y *= 0.125f; r.z *= 0.125f; r.w *= 0.125f;

    // d_skip already holds x + x@Wskip + bskip
    float4 sk = ((const float4*)(d_skip + (size_t)gw * DD))[lane];
    float4 o = make_float4(sk.x + r.x, sk.y + r.y, sk.z + r.z, sk.w + r.w);

    float s = o.x + o.y + o.z + o.w;
    float qq = o.x * o.x + o.y * o.y + o.z * o.z + o.w * o.w;
#pragma unroll
    for (int ofs = 16; ofs > 0; ofs >>= 1) {
        s  += __shfl_xor_sync(0xffffffffu, s, ofs);
        qq += __shfl_xor_sync(0xffffffffu, qq, ofs);
    }
    float mean = s * (1.0f / 128.0f);
    float var = qq * (1.0f / 128.0f) - mean * mean;
    float rs = rsqrtf(var + 1e-5f);
    float4 gg = ((const float4*)g1)[lane];
    float4 bb = ((const float4*)beta1)[lane];
    float4 hv;
    hv.x = (o.x - mean) * rs * gg.x + bb.x;
    hv.y = (o.y - mean) * rs * gg.y + bb.y;
    hv.z = (o.z - mean) * rs * gg.z + bb.z;
    hv.w = (o.w - mean) * rs * gg.w + bb.w;
    ((float4*)(d_h + (size_t)gw * DD))[lane] = hv;

    __nv_bfloat16* base = d_A2h + (size_t)gw * 3 * DD + lane * 4;
    float vals[4] = {hv.x, hv.y, hv.z, hv.w};
    __nv_bfloat162 hi2[2], lo2[2];
#pragma unroll
    for (int i = 0; i < 2; ++i) {
        __nv_bfloat16 h0 = __float2bfloat16(vals[2 * i]);
        __nv_bfloat16 h1 = __float2bfloat16(vals[2 * i + 1]);
        __nv_bfloat16 l0 = __float2bfloat16(vals[2 * i] - __bfloat162float(h0));
        __nv_bfloat16 l1 = __float2bfloat16(vals[2 * i + 1] - __bfloat162float(h1));
        hi2[i].x = h0; hi2[i].y = h1;
        lo2[i].x = l0; lo2[i].y = l1;
    }
    *(__nv_bfloat162*)(base) = hi2[0];
    *(__nv_bfloat162*)(base + 2) = hi2[1];
    *(__nv_bfloat162*)(base + DD) = hi2[0];
    *(__nv_bfloat162*)(base + DD + 2) = hi2[1];
    *(__nv_bfloat162*)(base + 2 * DD) = lo2[0];
    *(__nv_bfloat162*)(base + 2 * DD + 2) = lo2[1];
}

// ---------------- launcher --------------------------------------------------
extern "C" void kernel_launch(void* const* d_in, const int* in_sizes, int n_in,
                              void* d_out, int out_size)
{
    const float* x     = (const float*)d_in[0];
    const void*  ei    = d_in[1];
    const float* Wq    = (const float*)d_in[2];
    const float* bq    = (const float*)d_in[3];
    const float* Wk    = (const float*)d_in[4];
    const float* bk    = (const float*)d_in[5];
    const float* Wv    = (const float*)d_in[6];
    const float* bv    = (const float*)d_in[7];
    const float* Wskip = (const float*)d_in[8];
    const float* bskip = (const float*)d_in[9];
    const float* g1    = (const float*)d_in[10];
    const float* beta1 = (const float*)d_in[11];
    const float* W1    = (const float*)d_in[12];
    const float* b1    = (const float*)d_in[13];
    const float* W2    = (const float*)d_in[14];
    const float* b2    = (const float*)d_in[15];
    const float* g2    = (const float*)d_in[16];
    const float* beta2 = (const float*)d_in[17];
    float* out = (float*)d_out;

    void *pA2x, *pA2h, *pA2f, *pB2w1;
    cudaGetSymbolAddress(&pA2x, d_A2x);
    cudaGetSymbolAddress(&pA2h, d_A2h);
    cudaGetSymbolAddress(&pA2f, d_A2f);
    cudaGetSymbolAddress(&pB2w1, d_B2w1);

    static cudaStream_t s_side = nullptr;
    static cudaEvent_t s_fork = nullptr, s_join = nullptr;
    if (s_side == nullptr) {
        cudaStreamCreateWithFlags(&s_side, cudaStreamNonBlocking);
        cudaEventCreateWithFlags(&s_fork, cudaEventDisableTiming);
        cudaEventCreateWithFlags(&s_join, cudaEventDisableTiming);
        cudaFuncSetAttribute(mma_gemm_kernel,
                             cudaFuncAttributeMaxDynamicSharedMemorySize,
                             GEMM_SMEM_BYTES);
        cudaFuncSetAttribute(mma_qkv_kernel,
                             cudaFuncAttributeMaxDynamicSharedMemorySize,
                             GEMM_SMEM_BYTES);
        cudaFuncSetAttribute(mma_ffn2sk_kernel,
                             cudaFuncAttributeMaxDynamicSharedMemorySize,
                             GEMM_SMEM_BYTES);
    }

    const int MT = (NN + BM - 1) / BM;  // 79

    // fork: CSR chain + W1/W2 splits on side stream
    cudaEventRecord(s_fork, 0);
    cudaStreamWaitEvent(s_side, s_fork, 0);
    detect_kernel<<<1, 32, 0, s_side>>>(ei);
    hist_kernel<<<(EE + 255) / 256, 256, 0, s_side>>>(ei);
    scan_kernel<<<1, 1024, 0, s_side>>>();
    scatter_kernel<<<(EE + 255) / 256, 256, 0, s_side>>>(ei);
    splitSide_kernel<<<(SPLIT_SIDE + 255) / 256, 256, 0, s_side>>>(W1, W2);
    cudaEventRecord(s_join, s_side);

    // main stream
    splitMain_kernel<<<(SPLIT_MAIN + 255) / 256, 256>>>(x, Wq, Wk, Wv, Wskip);
    mma_qkv_kernel<<<dim3(25, MT), 256, GEMM_SMEM_BYTES>>>(
        (const __nv_bfloat16*)pA2x, x, bq, bk, bv, bskip, NN);

    cudaStreamWaitEvent(0, s_join, 0);

    attn_kernel<<<(NN * 32 + 127) / 128, 128>>>(g1, beta1);

    mma_gemm_kernel<<<dim3(FFD / BN, MT), 256, GEMM_SMEM_BYTES>>>(
        (const __nv_bfloat16*)pA2h, 3 * DD, 3 * DD, (const __nv_bfloat16*)pB2w1,
        FFD, b1, nullptr, nullptr, nullptr, (__nv_bfloat16*)pA2f, NN, 1);

    mma_ffn2sk_kernel<<<dim3(4, MT), 256, GEMM_SMEM_BYTES>>>(
        (const __nv_bfloat16*)pA2f, NN);

    ln2_reduce_kernel<<<(NN * 32 + 255) / 256, 256>>>(b2, g2, beta2, out);
}